// round 12
// baseline (speedup 1.0000x reference)
#include <cuda_runtime.h>
#include <cuda_bf16.h>
#include <mma.h>
#include <cstdint>

using namespace nvcuda;

// Shapes (fixed by the reference)
#define B_   32
#define C_   512
#define N_   1024       // H*W
#define M_   77
#define MP_  128        // padded M
#define TD_  768
#define NH_  8
#define HD_  64
#define SCALE_ 0.125f   // 1/sqrt(64)

// Scratch (static __device__ — allocation-free per harness rules)
__device__ float g_Qt[B_ * C_ * N_];     // 64 MB  Qt[b][c][n]  (tf32-rounded)
__device__ float g_Kt[B_ * C_ * MP_];    //  8 MB  (tf32-rounded)
__device__ float g_Vt[B_ * C_ * MP_];    //  8 MB  (tf32-rounded)
__device__ float g_Wqr[C_ * C_];         //  1 MB  tf32-rounded operands
__device__ float g_Wkr[C_ * TD_];
__device__ float g_Wvr[C_ * TD_];
__device__ float g_tr[B_ * M_ * TD_];    //  7.6 MB

// tf32 round-to-nearest
__device__ __forceinline__ float tf32r(float f) {
    uint32_t u;
    asm("cvt.rna.tf32.f32 %0, %1;" : "=r"(u) : "f"(f));
    return __uint_as_float(u);
}
__device__ __forceinline__ uint32_t smem_u32(const void* p) {
    uint32_t a;
    asm("{ .reg .u64 t; cvta.to.shared.u64 t, %1; cvt.u32.u64 %0, t; }"
        : "=r"(a) : "l"(p));
    return a;
}
__device__ __forceinline__ void cp16(uint32_t dst, const float* src) {
    asm volatile("cp.async.cg.shared.global [%0], [%1], 16;"
                 :: "r"(dst), "l"(src));
}
// zero-fill variant: src-size 0 -> 16 bytes of zeros, src not dereferenced
__device__ __forceinline__ void cp16z(uint32_t dst, const float* src, bool valid) {
    const int sz = valid ? 16 : 0;
    asm volatile("cp.async.cg.shared.global [%0], [%1], 16, %2;"
                 :: "r"(dst), "l"(src), "r"(sz));
}

// ---------------------------------------------------------------------------
// 0) Pre-round fp32 -> tf32 (weights + text), single merged launch
// ---------------------------------------------------------------------------
__global__ void round_all_kernel(const float* __restrict__ Wq,
                                 const float* __restrict__ Wk,
                                 const float* __restrict__ Wv,
                                 const float* __restrict__ text) {
    const int stride = gridDim.x * blockDim.x;
    const int gid = blockIdx.x * blockDim.x + threadIdx.x;
    const float* srcs[4] = { Wq, Wk, Wv, text };
    float* dsts[4] = { g_Wqr, g_Wkr, g_Wvr, g_tr };
    const int n4s[4] = { (C_ * C_) / 4, (C_ * TD_) / 4, (C_ * TD_) / 4,
                         (B_ * M_ * TD_) / 4 };
#pragma unroll
    for (int a = 0; a < 4; a++) {
        const float4* s = reinterpret_cast<const float4*>(srcs[a]);
        float4* d = reinterpret_cast<float4*>(dsts[a]);
        for (int i = gid; i < n4s[a]; i += stride) {
            float4 v = s[i];
            v.x = tf32r(v.x); v.y = tf32r(v.y); v.z = tf32r(v.z); v.w = tf32r(v.w);
            d[i] = v;
        }
    }
}

// ===========================================================================
// tf32 WMMA GEMM: C[m][n] = A[m][k] @ B + bias[m]
//   block 128x128, 8 warps (2m x 4n), warp tile 64x32 = 4x2 wmma frags
//   (R8 shape: 128 regs -> fits 2 blocks/SM = 16 warps/SM for latency hiding)
//   k-tile 32, double-buffered cp.async staging.
//   A pre-rounded tf32. BCVT: convert B fragments in-register (Q path, raw x).
//   Epilogue writes tf32-rounded C (consumed by tensor-core attention).
// ===========================================================================
#define A_LD   36
#define BQ_LD  132
#define BC_LD  36
#define A_FLOATS   (128 * A_LD)          // 4608
#define B_FLOATS   (128 * BC_LD)         // 4608 (>= 32*BQ_LD = 4224)
#define BUF_FLOATS (A_FLOATS + B_FLOATS) // 9216
#define GEMM_SMEM  (2 * BUF_FLOATS * 4)  // 73728 bytes

template<bool BCOL, bool BCVT>
__device__ __forceinline__ void gemm_body(
    const float* __restrict__ A, const float* __restrict__ Bsrc,
    float* __restrict__ Cout, const float* __restrict__ bias,
    int K, int lda, int ldb, int ldc)
{
    extern __shared__ float smem[];
    const uint32_t smem_addr = smem_u32(smem);
    const int tid = threadIdx.x;          // 256 threads
    const int wid = tid >> 5, lane = tid & 31;
    const int wm = wid >> 2, wn = wid & 3;        // 2 x 4 warp grid
    const int rowBase = blockIdx.y << 7;
    const int colBase = blockIdx.x << 7;

    wmma::fragment<wmma::accumulator, 16, 16, 8, float> c[4][2];
#pragma unroll
    for (int i = 0; i < 4; i++)
#pragma unroll
        for (int j = 0; j < 2; j++) wmma::fill_fragment(c[i][j], 0.0f);

    auto stage = [&](int kt, int buf) {
        const uint32_t sA = smem_addr + buf * (BUF_FLOATS * 4);
        const uint32_t sB = sA + A_FLOATS * 4;
        const float* baseA = A + (size_t)rowBase * lda + kt * 32;
#pragma unroll
        for (int r4 = 0; r4 < 4; r4++) {            // A tile: [128][32]
            const int i4 = tid + (r4 << 8);
            const int row = i4 >> 3, c4 = (i4 & 7) << 2;
            cp16(sA + (uint32_t)(row * A_LD + c4) * 4, baseA + (size_t)row * lda + c4);
        }
        if (!BCOL) {                                 // B tile: [k=32][n=128]
            const float* baseB = Bsrc + (size_t)(kt * 32) * ldb + colBase;
#pragma unroll
            for (int r4 = 0; r4 < 4; r4++) {
                const int i4 = tid + (r4 << 8);
                const int k = i4 >> 5, n4 = (i4 & 31) << 2;
                cp16(sB + (uint32_t)(k * BQ_LD + n4) * 4, baseB + (size_t)k * ldb + n4);
            }
        } else {                                     // B tile: [n=128][k=32], pad n>=M_
            const float* baseB = Bsrc + kt * 32;
#pragma unroll
            for (int r4 = 0; r4 < 4; r4++) {
                const int i4 = tid + (r4 << 8);
                const int n = i4 >> 3, k4 = (i4 & 7) << 2;
                cp16z(sB + (uint32_t)(n * BC_LD + k4) * 4, baseB + (size_t)n * ldb + k4,
                      n < M_);
            }
        }
    };

    const int nkt = K >> 5;
    stage(0, 0);
    asm volatile("cp.async.commit_group;" ::: "memory");

    for (int kt = 0; kt < nkt; kt++) {
        const int buf = kt & 1;
        if (kt + 1 < nkt) {
            stage(kt + 1, buf ^ 1);
            asm volatile("cp.async.commit_group;" ::: "memory");
            asm volatile("cp.async.wait_group 1;" ::: "memory");
        } else {
            asm volatile("cp.async.wait_group 0;" ::: "memory");
        }
        __syncthreads();

        const float* As = smem + buf * BUF_FLOATS;
        const float* Bs = As + A_FLOATS;
#pragma unroll
        for (int ks = 0; ks < 4; ks++) {
            wmma::fragment<wmma::matrix_a, 16, 16, 8, wmma::precision::tf32,
                           wmma::row_major> a[4];
#pragma unroll
            for (int i = 0; i < 4; i++)
                wmma::load_matrix_sync(a[i], As + (wm * 64 + i * 16) * A_LD + ks * 8, A_LD);
#pragma unroll
            for (int j = 0; j < 2; j++) {
                if (!BCOL) {
                    wmma::fragment<wmma::matrix_b, 16, 16, 8, wmma::precision::tf32,
                                   wmma::row_major> b;
                    wmma::load_matrix_sync(b, Bs + ks * 8 * BQ_LD + (wn * 32 + j * 16),
                                           BQ_LD);
                    if (BCVT) {
#pragma unroll
                        for (int t = 0; t < b.num_elements; t++)
                            b.x[t] = wmma::__float_to_tf32(b.x[t]);
                    }
#pragma unroll
                    for (int i = 0; i < 4; i++) wmma::mma_sync(c[i][j], a[i], b, c[i][j]);
                } else {
                    wmma::fragment<wmma::matrix_b, 16, 16, 8, wmma::precision::tf32,
                                   wmma::col_major> b;
                    wmma::load_matrix_sync(b, Bs + (wn * 32 + j * 16) * BC_LD + ks * 8,
                                           BC_LD);
                    if (BCVT) {
#pragma unroll
                        for (int t = 0; t < b.num_elements; t++)
                            b.x[t] = wmma::__float_to_tf32(b.x[t]);
                    }
#pragma unroll
                    for (int i = 0; i < 4; i++) wmma::mma_sync(c[i][j], a[i], b, c[i][j]);
                }
            }
        }
        __syncthreads();   // staging buffers free for next prefetch / epilogue
    }

    // Epilogue: per-warp 16x16 smem patch, add bias, tf32-round, write C
    float* patch = smem + wid * 256;
#pragma unroll
    for (int i = 0; i < 4; i++) {
        const int row0 = rowBase + wm * 64 + i * 16;
#pragma unroll
        for (int j = 0; j < 2; j++) {
            const int col0 = colBase + wn * 32 + j * 16;
            wmma::store_matrix_sync(patch, c[i][j], 16, wmma::mem_row_major);
            __syncwarp();
#pragma unroll
            for (int e = lane; e < 256; e += 32) {
                const int r = e >> 4, cc = e & 15;
                Cout[(size_t)(row0 + r) * ldc + col0 + cc] =
                    tf32r(patch[e] + bias[row0 + r]);
            }
            __syncwarp();
        }
    }
}

// Qt[b] = Wq(512x512) @ x[b](512x1024) + bq   grid (8, 4, 32); B = raw x (cvt in reg)
__global__ __launch_bounds__(256, 2)
void gemm_q_kernel(const float* __restrict__ x, const float* __restrict__ bq) {
    const int b = blockIdx.z;
    gemm_body<false, true>(g_Wqr, x + (size_t)b * C_ * N_, g_Qt + (size_t)b * C_ * N_,
                           bq, C_, C_, N_, N_);
}

// Kt/Vt[b] = W(512x768) @ text[b]^T + bias   grid (1, 4, 64), z = 2b+isV
__global__ __launch_bounds__(256, 2)
void gemm_kv_kernel(const float* __restrict__ bk, const float* __restrict__ bv) {
    const int z = blockIdx.z;
    const int b = z >> 1;
    const bool isV = (z & 1) != 0;
    gemm_body<true, false>(isV ? g_Wvr : g_Wkr, g_tr + (size_t)b * M_ * TD_,
                           (isV ? g_Vt : g_Kt) + (size_t)b * C_ * MP_,
                           isV ? bv : bk, TD_, TD_, TD_, MP_);
}

// ===========================================================================
// WMMA attention v3 (unchanged from R11): 256-query blocks, K/V in smem.
// ===========================================================================
#define S_LD  84
#define KV_LD 84
#define ATTN_SMEM_FLOATS (256 * S_LD + 2 * 64 * KV_LD + 80)
#define ATTN_SMEM_BYTES  (ATTN_SMEM_FLOATS * 4)    // 129344 B

__global__ __launch_bounds__(256)
void attn_kernel(const int* __restrict__ mask, float* __restrict__ out) {
    extern __shared__ float sm[];
    float* Ssm = sm;                         // [256][S_LD]
    float* Ks  = sm + 256 * S_LD;            // [64][KV_LD]  (d, m)
    float* Vs  = Ks + 64 * KV_LD;            // [64][KV_LD]  (d, m)
    float* msk = Vs + 64 * KV_LD;            // [80]

    const int tid = threadIdx.x;
    const int wid = tid >> 5;
    const int b = blockIdx.z, h = blockIdx.y;
    const int n0 = blockIdx.x << 8;          // 256-query tile

    const float* Qbase = g_Qt + ((size_t)(b * C_ + h * HD_)) * N_ + n0; // (n,d)=ptr[d*N_+n]
    const float* Kbase = g_Kt + ((size_t)(b * C_ + h * HD_)) * MP_;     // (d,m)=ptr[d*MP_+m]
    const float* Vbase = g_Vt + ((size_t)(b * C_ + h * HD_)) * MP_;

    // Stage K/V: 64 rows x 80 floats, coalesced float4 over m
    for (int i = tid; i < 64 * 20; i += 256) {
        const int d = i / 20, m4 = (i % 20) << 2;
        *reinterpret_cast<float4*>(&Ks[d * KV_LD + m4]) =
            *reinterpret_cast<const float4*>(Kbase + (size_t)d * MP_ + m4);
        *reinterpret_cast<float4*>(&Vs[d * KV_LD + m4]) =
            *reinterpret_cast<const float4*>(Vbase + (size_t)d * MP_ + m4);
    }
    if (tid < 80)
        msk[tid] = (tid < M_ && mask[b * M_ + tid] != 0) ? 0.0f : -1e30f;
    __syncthreads();

    // -------- Phase 1: S = Q @ K^T (warp w -> 32-row band) -------------------
    {
        wmma::fragment<wmma::accumulator, 16, 16, 8, float> sacc[2][5];
#pragma unroll
        for (int i = 0; i < 2; i++)
#pragma unroll
            for (int j = 0; j < 5; j++) wmma::fill_fragment(sacc[i][j], 0.0f);
#pragma unroll
        for (int kf = 0; kf < 8; kf++) {      // d = kf*8
            wmma::fragment<wmma::matrix_a, 16, 16, 8, wmma::precision::tf32,
                           wmma::col_major> a[2];
#pragma unroll
            for (int i = 0; i < 2; i++)
                wmma::load_matrix_sync(a[i],
                    Qbase + (size_t)(kf * 8) * N_ + wid * 32 + i * 16, N_);
#pragma unroll
            for (int j = 0; j < 5; j++) {
                wmma::fragment<wmma::matrix_b, 16, 16, 8, wmma::precision::tf32,
                               wmma::row_major> kb;
                wmma::load_matrix_sync(kb, Ks + (kf * 8) * KV_LD + j * 16, KV_LD);
#pragma unroll
                for (int i = 0; i < 2; i++) wmma::mma_sync(sacc[i][j], a[i], kb, sacc[i][j]);
            }
        }
#pragma unroll
        for (int i = 0; i < 2; i++)
#pragma unroll
            for (int j = 0; j < 5; j++)
                wmma::store_matrix_sync(Ssm + (wid * 32 + i * 16) * S_LD + j * 16,
                                        sacc[i][j], S_LD, wmma::mem_row_major);
    }
    __syncthreads();

    // -------- Softmax: one thread per query row ------------------------------
    {
        float* row = Ssm + tid * S_LD;
        float mx = -1e30f;
#pragma unroll 7
        for (int m = 0; m < M_; m++) {
            const float s = row[m] * SCALE_ + msk[m];
            row[m] = s;
            mx = fmaxf(mx, s);
        }
        float sum = 0.0f;
#pragma unroll 7
        for (int m = 0; m < M_; m++) {
            const float p = __expf(row[m] - mx);
            row[m] = p;
            sum += p;
        }
        const float inv = 1.0f / sum;
#pragma unroll 7
        for (int m = 0; m < M_; m++) row[m] = tf32r(row[m] * inv);
        row[77] = 0.0f; row[78] = 0.0f; row[79] = 0.0f;   // kill padded keys
    }
    __syncthreads();

    // -------- Phase 2: O = P @ V (warp w -> 32-row band, 4 d-frags) ----------
    {
        wmma::fragment<wmma::accumulator, 16, 16, 8, float> oacc[2][4];
#pragma unroll
        for (int i = 0; i < 2; i++)
#pragma unroll
            for (int j = 0; j < 4; j++) wmma::fill_fragment(oacc[i][j], 0.0f);
#pragma unroll
        for (int kf = 0; kf < 10; kf++) {     // m = kf*8
            wmma::fragment<wmma::matrix_a, 16, 16, 8, wmma::precision::tf32,
                           wmma::row_major> a[2];
#pragma unroll
            for (int i = 0; i < 2; i++)
                wmma::load_matrix_sync(a[i],
                    Ssm + (wid * 32 + i * 16) * S_LD + kf * 8, S_LD);
#pragma unroll
            for (int j = 0; j < 4; j++) {
                wmma::fragment<wmma::matrix_b, 16, 16, 8, wmma::precision::tf32,
                               wmma::col_major> vb;
                wmma::load_matrix_sync(vb, Vs + (j * 16) * KV_LD + kf * 8, KV_LD);
#pragma unroll
                for (int i = 0; i < 2; i++) wmma::mma_sync(oacc[i][j], a[i], vb, oacc[i][j]);
            }
        }
        float* obase = out + ((size_t)(b * C_ + h * HD_)) * N_ + n0 + wid * 32;
#pragma unroll
        for (int i = 0; i < 2; i++)
#pragma unroll
            for (int j = 0; j < 4; j++)
                wmma::store_matrix_sync(obase + i * 16 + (size_t)(j * 16) * N_,
                                        oacc[i][j], N_, wmma::mem_col_major);
    }
}

// ---------------------------------------------------------------------------
// kernel_launch — inputs: 0:x 1:text_emb 2:attention_mask 3:Wq 4:bq 5:Wk 6:bk 7:Wv 8:bv
// ---------------------------------------------------------------------------
extern "C" void kernel_launch(void* const* d_in, const int* in_sizes, int n_in,
                              void* d_out, int out_size) {
    (void)in_sizes; (void)n_in; (void)out_size;
    const float* x    = (const float*)d_in[0];
    const float* text = (const float*)d_in[1];
    const int*   mask = (const int*)d_in[2];
    const float* Wq   = (const float*)d_in[3];
    const float* bq   = (const float*)d_in[4];
    const float* Wk   = (const float*)d_in[5];
    const float* bk   = (const float*)d_in[6];
    const float* Wv   = (const float*)d_in[7];
    const float* bv   = (const float*)d_in[8];
    float* out = (float*)d_out;

    cudaFuncSetAttribute(gemm_q_kernel,  cudaFuncAttributeMaxDynamicSharedMemorySize,
                         GEMM_SMEM);
    cudaFuncSetAttribute(gemm_kv_kernel, cudaFuncAttributeMaxDynamicSharedMemorySize,
                         GEMM_SMEM);
    cudaFuncSetAttribute(attn_kernel, cudaFuncAttributeMaxDynamicSharedMemorySize,
                         ATTN_SMEM_BYTES);

    round_all_kernel<<<1184, 256>>>(Wq, Wk, Wv, text);
    gemm_kv_kernel<<<dim3(1, 4, 64), 256, GEMM_SMEM>>>(bk, bv);
    gemm_q_kernel<<<dim3(8, 4, 32), 256, GEMM_SMEM>>>(x, bq);
    attn_kernel<<<dim3(4, 8, 32), 256, ATTN_SMEM_BYTES>>>(mask, out);
}

// round 13
// speedup vs baseline: 1.0573x; 1.0573x over previous
#include <cuda_runtime.h>
#include <cuda_bf16.h>
#include <mma.h>
#include <cstdint>

using namespace nvcuda;

// Shapes (fixed by the reference)
#define B_   32
#define C_   512
#define N_   1024       // H*W
#define M_   77
#define MP_  128        // padded M
#define TD_  768
#define NH_  8
#define HD_  64
#define SCALE_ 0.125f   // 1/sqrt(64)

// Scratch (static __device__ — allocation-free per harness rules)
__device__ float g_Qt[B_ * C_ * N_];     // 64 MB  Qt[b][c][n]  (tf32-rounded)
__device__ float g_Kt[B_ * C_ * MP_];    //  8 MB  (tf32-rounded)
__device__ float g_Vt[B_ * C_ * MP_];    //  8 MB  (tf32-rounded)
__device__ float g_Wqr[C_ * C_];         //  1 MB  tf32-rounded operands
__device__ float g_Wkr[C_ * TD_];
__device__ float g_Wvr[C_ * TD_];
__device__ float g_tr[B_ * M_ * TD_];    //  7.6 MB

// tf32 round-to-nearest
__device__ __forceinline__ float tf32r(float f) {
    uint32_t u;
    asm("cvt.rna.tf32.f32 %0, %1;" : "=r"(u) : "f"(f));
    return __uint_as_float(u);
}
__device__ __forceinline__ uint32_t smem_u32(const void* p) {
    uint32_t a;
    asm("{ .reg .u64 t; cvta.to.shared.u64 t, %1; cvt.u32.u64 %0, t; }"
        : "=r"(a) : "l"(p));
    return a;
}
__device__ __forceinline__ void cp16(uint32_t dst, const float* src) {
    asm volatile("cp.async.cg.shared.global [%0], [%1], 16;"
                 :: "r"(dst), "l"(src));
}
// zero-fill variant: src-size 0 -> 16 bytes of zeros, src not dereferenced
__device__ __forceinline__ void cp16z(uint32_t dst, const float* src, bool valid) {
    const int sz = valid ? 16 : 0;
    asm volatile("cp.async.cg.shared.global [%0], [%1], 16, %2;"
                 :: "r"(dst), "l"(src), "r"(sz));
}

// ---------------------------------------------------------------------------
// 0) Pre-round fp32 -> tf32 (weights + text), single merged launch
// ---------------------------------------------------------------------------
__global__ void round_all_kernel(const float* __restrict__ Wq,
                                 const float* __restrict__ Wk,
                                 const float* __restrict__ Wv,
                                 const float* __restrict__ text) {
    const int stride = gridDim.x * blockDim.x;
    const int gid = blockIdx.x * blockDim.x + threadIdx.x;
    const float* srcs[4] = { Wq, Wk, Wv, text };
    float* dsts[4] = { g_Wqr, g_Wkr, g_Wvr, g_tr };
    const int n4s[4] = { (C_ * C_) / 4, (C_ * TD_) / 4, (C_ * TD_) / 4,
                         (B_ * M_ * TD_) / 4 };
#pragma unroll
    for (int a = 0; a < 4; a++) {
        const float4* s = reinterpret_cast<const float4*>(srcs[a]);
        float4* d = reinterpret_cast<float4*>(dsts[a]);
        for (int i = gid; i < n4s[a]; i += stride) {
            float4 v = s[i];
            v.x = tf32r(v.x); v.y = tf32r(v.y); v.z = tf32r(v.z); v.w = tf32r(v.w);
            d[i] = v;
        }
    }
}

// ===========================================================================
// tf32 WMMA GEMM (R11 config — measured best): C[m][n] = A[m][k] @ B + bias[m]
//   block 128x128, 4 warps (2m x 2n), warp tile 64x64 = 4x4 wmma frags,
//   k-tile 32, double-buffered cp.async staging, 2 blocks/SM.
//   A pre-rounded tf32. BCVT: convert B fragments in-register (Q path, raw x).
//   Epilogue writes tf32-rounded C (consumed by tensor-core attention).
// ===========================================================================
#define A_LD   36
#define BQ_LD  132
#define BC_LD  36
#define A_FLOATS   (128 * A_LD)          // 4608
#define B_FLOATS   (128 * BC_LD)         // 4608 (>= 32*BQ_LD = 4224)
#define BUF_FLOATS (A_FLOATS + B_FLOATS) // 9216
#define GEMM_SMEM  (2 * BUF_FLOATS * 4)  // 73728 bytes

template<bool BCOL, bool BCVT>
__device__ __forceinline__ void gemm_body(
    const float* __restrict__ A, const float* __restrict__ Bsrc,
    float* __restrict__ Cout, const float* __restrict__ bias,
    int K, int lda, int ldb, int ldc)
{
    extern __shared__ float smem[];
    const uint32_t smem_addr = smem_u32(smem);
    const int tid = threadIdx.x;          // 128 threads
    const int wid = tid >> 5, lane = tid & 31;
    const int wm = wid >> 1, wn = wid & 1;        // 2 x 2 warp grid
    const int rowBase = blockIdx.y << 7;
    const int colBase = blockIdx.x << 7;

    wmma::fragment<wmma::accumulator, 16, 16, 8, float> c[4][4];
#pragma unroll
    for (int i = 0; i < 4; i++)
#pragma unroll
        for (int j = 0; j < 4; j++) wmma::fill_fragment(c[i][j], 0.0f);

    auto stage = [&](int kt, int buf) {
        const uint32_t sA = smem_addr + buf * (BUF_FLOATS * 4);
        const uint32_t sB = sA + A_FLOATS * 4;
        const float* baseA = A + (size_t)rowBase * lda + kt * 32;
#pragma unroll
        for (int r4 = 0; r4 < 8; r4++) {            // A tile: [128][32]
            const int i4 = tid + (r4 << 7);
            const int row = i4 >> 3, c4 = (i4 & 7) << 2;
            cp16(sA + (uint32_t)(row * A_LD + c4) * 4, baseA + (size_t)row * lda + c4);
        }
        if (!BCOL) {                                 // B tile: [k=32][n=128]
            const float* baseB = Bsrc + (size_t)(kt * 32) * ldb + colBase;
#pragma unroll
            for (int r4 = 0; r4 < 8; r4++) {
                const int i4 = tid + (r4 << 7);
                const int k = i4 >> 5, n4 = (i4 & 31) << 2;
                cp16(sB + (uint32_t)(k * BQ_LD + n4) * 4, baseB + (size_t)k * ldb + n4);
            }
        } else {                                     // B tile: [n=128][k=32], pad n>=M_
            const float* baseB = Bsrc + kt * 32;
#pragma unroll
            for (int r4 = 0; r4 < 8; r4++) {
                const int i4 = tid + (r4 << 7);
                const int n = i4 >> 3, k4 = (i4 & 7) << 2;
                cp16z(sB + (uint32_t)(n * BC_LD + k4) * 4, baseB + (size_t)n * ldb + k4,
                      n < M_);
            }
        }
    };

    const int nkt = K >> 5;
    stage(0, 0);
    asm volatile("cp.async.commit_group;" ::: "memory");

    for (int kt = 0; kt < nkt; kt++) {
        const int buf = kt & 1;
        if (kt + 1 < nkt) {
            stage(kt + 1, buf ^ 1);
            asm volatile("cp.async.commit_group;" ::: "memory");
            asm volatile("cp.async.wait_group 1;" ::: "memory");
        } else {
            asm volatile("cp.async.wait_group 0;" ::: "memory");
        }
        __syncthreads();

        const float* As = smem + buf * BUF_FLOATS;
        const float* Bs = As + A_FLOATS;
#pragma unroll
        for (int ks = 0; ks < 4; ks++) {
            wmma::fragment<wmma::matrix_a, 16, 16, 8, wmma::precision::tf32,
                           wmma::row_major> a[4];
#pragma unroll
            for (int i = 0; i < 4; i++)
                wmma::load_matrix_sync(a[i], As + (wm * 64 + i * 16) * A_LD + ks * 8, A_LD);
#pragma unroll
            for (int j = 0; j < 4; j++) {
                if (!BCOL) {
                    wmma::fragment<wmma::matrix_b, 16, 16, 8, wmma::precision::tf32,
                                   wmma::row_major> b;
                    wmma::load_matrix_sync(b, Bs + ks * 8 * BQ_LD + (wn * 64 + j * 16),
                                           BQ_LD);
                    if (BCVT) {
#pragma unroll
                        for (int t = 0; t < b.num_elements; t++)
                            b.x[t] = wmma::__float_to_tf32(b.x[t]);
                    }
#pragma unroll
                    for (int i = 0; i < 4; i++) wmma::mma_sync(c[i][j], a[i], b, c[i][j]);
                } else {
                    wmma::fragment<wmma::matrix_b, 16, 16, 8, wmma::precision::tf32,
                                   wmma::col_major> b;
                    wmma::load_matrix_sync(b, Bs + (wn * 64 + j * 16) * BC_LD + ks * 8,
                                           BC_LD);
                    if (BCVT) {
#pragma unroll
                        for (int t = 0; t < b.num_elements; t++)
                            b.x[t] = wmma::__float_to_tf32(b.x[t]);
                    }
#pragma unroll
                    for (int i = 0; i < 4; i++) wmma::mma_sync(c[i][j], a[i], b, c[i][j]);
                }
            }
        }
        __syncthreads();   // staging buffers free for next prefetch / epilogue
    }

    // Epilogue: per-warp 16x16 smem patch, add bias, tf32-round, write C
    float* patch = smem + wid * 256;
#pragma unroll
    for (int i = 0; i < 4; i++) {
        const int row0 = rowBase + wm * 64 + i * 16;
#pragma unroll
        for (int j = 0; j < 4; j++) {
            const int col0 = colBase + wn * 64 + j * 16;
            wmma::store_matrix_sync(patch, c[i][j], 16, wmma::mem_row_major);
            __syncwarp();
#pragma unroll
            for (int e = lane; e < 256; e += 32) {
                const int r = e >> 4, cc = e & 15;
                Cout[(size_t)(row0 + r) * ldc + col0 + cc] =
                    tf32r(patch[e] + bias[row0 + r]);
            }
            __syncwarp();
        }
    }
}

// Qt[b] = Wq(512x512) @ x[b](512x1024) + bq   grid (8, 4, 32); B = raw x (cvt in reg)
__global__ __launch_bounds__(128, 2)
void gemm_q_kernel(const float* __restrict__ x, const float* __restrict__ bq) {
    const int b = blockIdx.z;
    gemm_body<false, true>(g_Wqr, x + (size_t)b * C_ * N_, g_Qt + (size_t)b * C_ * N_,
                           bq, C_, C_, N_, N_);
}

// Kt/Vt[b] = W(512x768) @ text[b]^T + bias   grid (1, 4, 64), z = 2b+isV
__global__ __launch_bounds__(128, 2)
void gemm_kv_kernel(const float* __restrict__ bk, const float* __restrict__ bv) {
    const int z = blockIdx.z;
    const int b = z >> 1;
    const bool isV = (z & 1) != 0;
    gemm_body<true, false>(isV ? g_Wvr : g_Wkr, g_tr + (size_t)b * M_ * TD_,
                           (isV ? g_Vt : g_Kt) + (size_t)b * C_ * MP_,
                           isV ? bv : bk, TD_, TD_, TD_, MP_);
}

// ===========================================================================
// WMMA attention v4: 128-query blocks (grid 4096), 256 thr (8 warps),
//   16-row band per warp (HALF the accumulator registers of v3 -> <=128 regs
//   -> 2 blocks/SM, 16 warps/SM), K/V staged once into smem (v3's win kept).
//   Phase 1: S[128][80] = Q·K^T; softmax SIMT one thread/row; Phase 2: O=P·V
//   stored col_major DIRECTLY into out ([B][C][H][W]).
// ===========================================================================
#define S_LD  84
#define KV_LD 84
#define ATTN_SMEM_FLOATS (128 * S_LD + 2 * 64 * KV_LD + 80)
#define ATTN_SMEM_BYTES  (ATTN_SMEM_FLOATS * 4)    // 86336 B -> 2 blocks/SM

__global__ __launch_bounds__(256, 2)
void attn_kernel(const int* __restrict__ mask, float* __restrict__ out) {
    extern __shared__ float sm[];
    float* Ssm = sm;                         // [128][S_LD]
    float* Ks  = sm + 128 * S_LD;            // [64][KV_LD]  (d, m)
    float* Vs  = Ks + 64 * KV_LD;            // [64][KV_LD]  (d, m)
    float* msk = Vs + 64 * KV_LD;            // [80]

    const int tid = threadIdx.x;
    const int wid = tid >> 5;
    const int b = blockIdx.z, h = blockIdx.y;
    const int n0 = blockIdx.x << 7;          // 128-query tile

    const float* Qbase = g_Qt + ((size_t)(b * C_ + h * HD_)) * N_ + n0; // (n,d)=ptr[d*N_+n]
    const float* Kbase = g_Kt + ((size_t)(b * C_ + h * HD_)) * MP_;     // (d,m)=ptr[d*MP_+m]
    const float* Vbase = g_Vt + ((size_t)(b * C_ + h * HD_)) * MP_;

    // Stage K/V: 64 rows x 80 floats, coalesced float4 over m
    for (int i = tid; i < 64 * 20; i += 256) {
        const int d = i / 20, m4 = (i % 20) << 2;
        *reinterpret_cast<float4*>(&Ks[d * KV_LD + m4]) =
            *reinterpret_cast<const float4*>(Kbase + (size_t)d * MP_ + m4);
        *reinterpret_cast<float4*>(&Vs[d * KV_LD + m4]) =
            *reinterpret_cast<const float4*>(Vbase + (size_t)d * MP_ + m4);
    }
    if (tid < 80)
        msk[tid] = (tid < M_ && mask[b * M_ + tid] != 0) ? 0.0f : -1e30f;
    __syncthreads();

    // -------- Phase 1: S = Q @ K^T (warp w -> 16-row band, 5 col frags) ------
    {
        wmma::fragment<wmma::accumulator, 16, 16, 8, float> sacc[5];
#pragma unroll
        for (int j = 0; j < 5; j++) wmma::fill_fragment(sacc[j], 0.0f);
#pragma unroll
        for (int kf = 0; kf < 8; kf++) {      // d = kf*8
            wmma::fragment<wmma::matrix_a, 16, 16, 8, wmma::precision::tf32,
                           wmma::col_major> a;
            wmma::load_matrix_sync(a, Qbase + (size_t)(kf * 8) * N_ + wid * 16, N_);
#pragma unroll
            for (int j = 0; j < 5; j++) {
                wmma::fragment<wmma::matrix_b, 16, 16, 8, wmma::precision::tf32,
                               wmma::row_major> kb;
                wmma::load_matrix_sync(kb, Ks + (kf * 8) * KV_LD + j * 16, KV_LD);
                wmma::mma_sync(sacc[j], a, kb, sacc[j]);
            }
        }
#pragma unroll
        for (int j = 0; j < 5; j++)
            wmma::store_matrix_sync(Ssm + (wid * 16) * S_LD + j * 16, sacc[j],
                                    S_LD, wmma::mem_row_major);
    }
    __syncthreads();

    // -------- Softmax: one thread per query row ------------------------------
    if (tid < 128) {
        float* row = Ssm + tid * S_LD;
        float mx = -1e30f;
#pragma unroll 7
        for (int m = 0; m < M_; m++) {
            const float s = row[m] * SCALE_ + msk[m];
            row[m] = s;
            mx = fmaxf(mx, s);
        }
        float sum = 0.0f;
#pragma unroll 7
        for (int m = 0; m < M_; m++) {
            const float p = __expf(row[m] - mx);
            row[m] = p;
            sum += p;
        }
        const float inv = 1.0f / sum;
#pragma unroll 7
        for (int m = 0; m < M_; m++) row[m] = tf32r(row[m] * inv);
        row[77] = 0.0f; row[78] = 0.0f; row[79] = 0.0f;   // kill padded keys
    }
    __syncthreads();

    // -------- Phase 2: O = P @ V (warp w -> 16-row band, 4 d-frags) ----------
    {
        wmma::fragment<wmma::accumulator, 16, 16, 8, float> oacc[4];
#pragma unroll
        for (int j = 0; j < 4; j++) wmma::fill_fragment(oacc[j], 0.0f);
#pragma unroll
        for (int kf = 0; kf < 10; kf++) {     // m = kf*8
            wmma::fragment<wmma::matrix_a, 16, 16, 8, wmma::precision::tf32,
                           wmma::row_major> a;
            wmma::load_matrix_sync(a, Ssm + (wid * 16) * S_LD + kf * 8, S_LD);
#pragma unroll
            for (int j = 0; j < 4; j++) {
                wmma::fragment<wmma::matrix_b, 16, 16, 8, wmma::precision::tf32,
                               wmma::col_major> vb;
                wmma::load_matrix_sync(vb, Vs + (j * 16) * KV_LD + kf * 8, KV_LD);
                wmma::mma_sync(oacc[j], a, vb, oacc[j]);
            }
        }
        float* obase = out + ((size_t)(b * C_ + h * HD_)) * N_ + n0 + wid * 16;
#pragma unroll
        for (int j = 0; j < 4; j++)
            wmma::store_matrix_sync(obase + (size_t)(j * 16) * N_, oacc[j],
                                    N_, wmma::mem_col_major);
    }
}

// ---------------------------------------------------------------------------
// kernel_launch — inputs: 0:x 1:text_emb 2:attention_mask 3:Wq 4:bq 5:Wk 6:bk 7:Wv 8:bv
// ---------------------------------------------------------------------------
extern "C" void kernel_launch(void* const* d_in, const int* in_sizes, int n_in,
                              void* d_out, int out_size) {
    (void)in_sizes; (void)n_in; (void)out_size;
    const float* x    = (const float*)d_in[0];
    const float* text = (const float*)d_in[1];
    const int*   mask = (const int*)d_in[2];
    const float* Wq   = (const float*)d_in[3];
    const float* bq   = (const float*)d_in[4];
    const float* Wk   = (const float*)d_in[5];
    const float* bk   = (const float*)d_in[6];
    const float* Wv   = (const float*)d_in[7];
    const float* bv   = (const float*)d_in[8];
    float* out = (float*)d_out;

    cudaFuncSetAttribute(gemm_q_kernel,  cudaFuncAttributeMaxDynamicSharedMemorySize,
                         GEMM_SMEM);
    cudaFuncSetAttribute(gemm_kv_kernel, cudaFuncAttributeMaxDynamicSharedMemorySize,
                         GEMM_SMEM);
    cudaFuncSetAttribute(attn_kernel, cudaFuncAttributeMaxDynamicSharedMemorySize,
                         ATTN_SMEM_BYTES);

    round_all_kernel<<<1184, 256>>>(Wq, Wk, Wv, text);
    gemm_kv_kernel<<<dim3(1, 4, 64), 128, GEMM_SMEM>>>(bk, bv);
    gemm_q_kernel<<<dim3(8, 4, 32), 128, GEMM_SMEM>>>(x, bq);
    attn_kernel<<<dim3(8, 8, 32), 256, ATTN_SMEM_BYTES>>>(mask, out);
}

// round 14
// speedup vs baseline: 1.0948x; 1.0355x over previous
#include <cuda_runtime.h>
#include <cuda_bf16.h>
#include <mma.h>
#include <cstdint>

using namespace nvcuda;

// Shapes (fixed by the reference)
#define B_   32
#define C_   512
#define N_   1024       // H*W
#define M_   77
#define MP_  128        // padded M
#define TD_  768
#define NH_  8
#define HD_  64
#define SCALE_ 0.125f   // 1/sqrt(64)

// Scratch (static __device__ — allocation-free per harness rules)
__device__ float g_Qt[B_ * C_ * N_];     // 64 MB  Qt[b][c][n]  (tf32-rounded)
__device__ float g_Kt[B_ * C_ * MP_];    //  8 MB  (tf32-rounded)
__device__ float g_Vt[B_ * C_ * MP_];    //  8 MB  (tf32-rounded)
__device__ float g_Wqr[C_ * C_];         //  1 MB  tf32-rounded operands
__device__ float g_Wkr[C_ * TD_];
__device__ float g_Wvr[C_ * TD_];
__device__ float g_tr[B_ * M_ * TD_];    //  7.6 MB

// tf32 round-to-nearest
__device__ __forceinline__ float tf32r(float f) {
    uint32_t u;
    asm("cvt.rna.tf32.f32 %0, %1;" : "=r"(u) : "f"(f));
    return __uint_as_float(u);
}
__device__ __forceinline__ uint32_t smem_u32(const void* p) {
    uint32_t a;
    asm("{ .reg .u64 t; cvta.to.shared.u64 t, %1; cvt.u32.u64 %0, t; }"
        : "=r"(a) : "l"(p));
    return a;
}
__device__ __forceinline__ void cp16(uint32_t dst, const float* src) {
    asm volatile("cp.async.cg.shared.global [%0], [%1], 16;"
                 :: "r"(dst), "l"(src));
}
// zero-fill variant: src-size 0 -> 16 bytes of zeros, src not dereferenced
__device__ __forceinline__ void cp16z(uint32_t dst, const float* src, bool valid) {
    const int sz = valid ? 16 : 0;
    asm volatile("cp.async.cg.shared.global [%0], [%1], 16, %2;"
                 :: "r"(dst), "l"(src), "r"(sz));
}

// ---------------------------------------------------------------------------
// 0) Pre-round fp32 -> tf32 (weights + text), single merged launch
// ---------------------------------------------------------------------------
__global__ void round_all_kernel(const float* __restrict__ Wq,
                                 const float* __restrict__ Wk,
                                 const float* __restrict__ Wv,
                                 const float* __restrict__ text) {
    const int stride = gridDim.x * blockDim.x;
    const int gid = blockIdx.x * blockDim.x + threadIdx.x;
    const float* srcs[4] = { Wq, Wk, Wv, text };
    float* dsts[4] = { g_Wqr, g_Wkr, g_Wvr, g_tr };
    const int n4s[4] = { (C_ * C_) / 4, (C_ * TD_) / 4, (C_ * TD_) / 4,
                         (B_ * M_ * TD_) / 4 };
#pragma unroll
    for (int a = 0; a < 4; a++) {
        const float4* s = reinterpret_cast<const float4*>(srcs[a]);
        float4* d = reinterpret_cast<float4*>(dsts[a]);
        for (int i = gid; i < n4s[a]; i += stride) {
            float4 v = s[i];
            v.x = tf32r(v.x); v.y = tf32r(v.y); v.z = tf32r(v.z); v.w = tf32r(v.w);
            d[i] = v;
        }
    }
}

// ===========================================================================
// tf32 WMMA GEMM (R11 config — measured best): C[m][n] = A[m][k] @ B + bias[m]
//   block 128x128, 4 warps (2m x 2n), warp tile 64x64 = 4x4 wmma frags,
//   k-tile 32, double-buffered cp.async staging, 2 blocks/SM.
//   A pre-rounded tf32. BCVT: convert B fragments in-register (Q path, raw x).
//   Epilogue writes tf32-rounded C (consumed by tensor-core attention).
// ===========================================================================
#define A_LD   36
#define BQ_LD  132
#define BC_LD  36
#define A_FLOATS   (128 * A_LD)          // 4608
#define B_FLOATS   (128 * BC_LD)         // 4608 (>= 32*BQ_LD = 4224)
#define BUF_FLOATS (A_FLOATS + B_FLOATS) // 9216
#define GEMM_SMEM  (2 * BUF_FLOATS * 4)  // 73728 bytes

template<bool BCOL, bool BCVT>
__device__ __forceinline__ void gemm_body(
    const float* __restrict__ A, const float* __restrict__ Bsrc,
    float* __restrict__ Cout, const float* __restrict__ bias,
    int K, int lda, int ldb, int ldc)
{
    extern __shared__ float smem[];
    const uint32_t smem_addr = smem_u32(smem);
    const int tid = threadIdx.x;          // 128 threads
    const int wid = tid >> 5, lane = tid & 31;
    const int wm = wid >> 1, wn = wid & 1;        // 2 x 2 warp grid
    const int rowBase = blockIdx.y << 7;
    const int colBase = blockIdx.x << 7;

    wmma::fragment<wmma::accumulator, 16, 16, 8, float> c[4][4];
#pragma unroll
    for (int i = 0; i < 4; i++)
#pragma unroll
        for (int j = 0; j < 4; j++) wmma::fill_fragment(c[i][j], 0.0f);

    auto stage = [&](int kt, int buf) {
        const uint32_t sA = smem_addr + buf * (BUF_FLOATS * 4);
        const uint32_t sB = sA + A_FLOATS * 4;
        const float* baseA = A + (size_t)rowBase * lda + kt * 32;
#pragma unroll
        for (int r4 = 0; r4 < 8; r4++) {            // A tile: [128][32]
            const int i4 = tid + (r4 << 7);
            const int row = i4 >> 3, c4 = (i4 & 7) << 2;
            cp16(sA + (uint32_t)(row * A_LD + c4) * 4, baseA + (size_t)row * lda + c4);
        }
        if (!BCOL) {                                 // B tile: [k=32][n=128]
            const float* baseB = Bsrc + (size_t)(kt * 32) * ldb + colBase;
#pragma unroll
            for (int r4 = 0; r4 < 8; r4++) {
                const int i4 = tid + (r4 << 7);
                const int k = i4 >> 5, n4 = (i4 & 31) << 2;
                cp16(sB + (uint32_t)(k * BQ_LD + n4) * 4, baseB + (size_t)k * ldb + n4);
            }
        } else {                                     // B tile: [n=128][k=32], pad n>=M_
            const float* baseB = Bsrc + kt * 32;
#pragma unroll
            for (int r4 = 0; r4 < 8; r4++) {
                const int i4 = tid + (r4 << 7);
                const int n = i4 >> 3, k4 = (i4 & 7) << 2;
                cp16z(sB + (uint32_t)(n * BC_LD + k4) * 4, baseB + (size_t)n * ldb + k4,
                      n < M_);
            }
        }
    };

    const int nkt = K >> 5;
    stage(0, 0);
    asm volatile("cp.async.commit_group;" ::: "memory");

    for (int kt = 0; kt < nkt; kt++) {
        const int buf = kt & 1;
        if (kt + 1 < nkt) {
            stage(kt + 1, buf ^ 1);
            asm volatile("cp.async.commit_group;" ::: "memory");
            asm volatile("cp.async.wait_group 1;" ::: "memory");
        } else {
            asm volatile("cp.async.wait_group 0;" ::: "memory");
        }
        __syncthreads();

        const float* As = smem + buf * BUF_FLOATS;
        const float* Bs = As + A_FLOATS;
#pragma unroll
        for (int ks = 0; ks < 4; ks++) {
            wmma::fragment<wmma::matrix_a, 16, 16, 8, wmma::precision::tf32,
                           wmma::row_major> a[4];
#pragma unroll
            for (int i = 0; i < 4; i++)
                wmma::load_matrix_sync(a[i], As + (wm * 64 + i * 16) * A_LD + ks * 8, A_LD);
#pragma unroll
            for (int j = 0; j < 4; j++) {
                if (!BCOL) {
                    wmma::fragment<wmma::matrix_b, 16, 16, 8, wmma::precision::tf32,
                                   wmma::row_major> b;
                    wmma::load_matrix_sync(b, Bs + ks * 8 * BQ_LD + (wn * 64 + j * 16),
                                           BQ_LD);
                    if (BCVT) {
#pragma unroll
                        for (int t = 0; t < b.num_elements; t++)
                            b.x[t] = wmma::__float_to_tf32(b.x[t]);
                    }
#pragma unroll
                    for (int i = 0; i < 4; i++) wmma::mma_sync(c[i][j], a[i], b, c[i][j]);
                } else {
                    wmma::fragment<wmma::matrix_b, 16, 16, 8, wmma::precision::tf32,
                                   wmma::col_major> b;
                    wmma::load_matrix_sync(b, Bs + (wn * 64 + j * 16) * BC_LD + ks * 8,
                                           BC_LD);
                    if (BCVT) {
#pragma unroll
                        for (int t = 0; t < b.num_elements; t++)
                            b.x[t] = wmma::__float_to_tf32(b.x[t]);
                    }
#pragma unroll
                    for (int i = 0; i < 4; i++) wmma::mma_sync(c[i][j], a[i], b, c[i][j]);
                }
            }
        }
        __syncthreads();   // staging buffers free for next prefetch / epilogue
    }

    // Epilogue: per-warp 16x16 smem patch, add bias, tf32-round, write C
    float* patch = smem + wid * 256;
#pragma unroll
    for (int i = 0; i < 4; i++) {
        const int row0 = rowBase + wm * 64 + i * 16;
#pragma unroll
        for (int j = 0; j < 4; j++) {
            const int col0 = colBase + wn * 64 + j * 16;
            wmma::store_matrix_sync(patch, c[i][j], 16, wmma::mem_row_major);
            __syncwarp();
#pragma unroll
            for (int e = lane; e < 256; e += 32) {
                const int r = e >> 4, cc = e & 15;
                Cout[(size_t)(row0 + r) * ldc + col0 + cc] =
                    tf32r(patch[e] + bias[row0 + r]);
            }
            __syncwarp();
        }
    }
}

// Qt[b] = Wq(512x512) @ x[b](512x1024) + bq   grid (8, 4, 32); B = raw x (cvt in reg)
__global__ __launch_bounds__(128, 2)
void gemm_q_kernel(const float* __restrict__ x, const float* __restrict__ bq) {
    const int b = blockIdx.z;
    gemm_body<false, true>(g_Wqr, x + (size_t)b * C_ * N_, g_Qt + (size_t)b * C_ * N_,
                           bq, C_, C_, N_, N_);
}

// Kt/Vt[b] = W(512x768) @ text[b]^T + bias   grid (1, 4, 64), z = 2b+isV
__global__ __launch_bounds__(128, 2)
void gemm_kv_kernel(const float* __restrict__ bk, const float* __restrict__ bv) {
    const int z = blockIdx.z;
    const int b = z >> 1;
    const bool isV = (z & 1) != 0;
    gemm_body<true, false>(isV ? g_Wvr : g_Wkr, g_tr + (size_t)b * M_ * TD_,
                           (isV ? g_Vt : g_Kt) + (size_t)b * C_ * MP_,
                           isV ? bv : bk, TD_, TD_, TD_, MP_);
}

// ===========================================================================
// WMMA attention v5: 128-query blocks, 256 thr (8 warps), 16-row bands,
//   K/V staged in smem; S stored COLUMN-MAJOR: S(q,m) at Ssm[q + m*SQ_LD].
//   -> softmax scans are bank-conflict-FREE (fixed m: banks = q mod 32),
//   -> Phase-2 A operand is exactly matrix_a col_major with ld SQ_LD.
// ===========================================================================
#define SQ_LD 132   // rows-per-column stride (>=128, mult of 4 for wmma ldm)
#define KV_LD 84
#define S_FLOATS (SQ_LD * 80)                       // 10560
#define ATTN_SMEM_FLOATS (S_FLOATS + 2 * 64 * KV_LD + 80)
#define ATTN_SMEM_BYTES  (ATTN_SMEM_FLOATS * 4)     // 85568 B -> 2 blocks/SM

__global__ __launch_bounds__(256, 2)
void attn_kernel(const int* __restrict__ mask, float* __restrict__ out) {
    extern __shared__ float sm[];
    float* Ssm = sm;                         // S(q,m) = Ssm[q + m*SQ_LD]
    float* Ks  = sm + S_FLOATS;              // [64][KV_LD]  (d, m)
    float* Vs  = Ks + 64 * KV_LD;            // [64][KV_LD]  (d, m)
    float* msk = Vs + 64 * KV_LD;            // [80]

    const int tid = threadIdx.x;
    const int wid = tid >> 5;
    const int b = blockIdx.z, h = blockIdx.y;
    const int n0 = blockIdx.x << 7;          // 128-query tile

    const float* Qbase = g_Qt + ((size_t)(b * C_ + h * HD_)) * N_ + n0; // (n,d)=ptr[d*N_+n]
    const float* Kbase = g_Kt + ((size_t)(b * C_ + h * HD_)) * MP_;     // (d,m)=ptr[d*MP_+m]
    const float* Vbase = g_Vt + ((size_t)(b * C_ + h * HD_)) * MP_;

    // Stage K/V: 64 rows x 80 floats, coalesced float4 over m
    for (int i = tid; i < 64 * 20; i += 256) {
        const int d = i / 20, m4 = (i % 20) << 2;
        *reinterpret_cast<float4*>(&Ks[d * KV_LD + m4]) =
            *reinterpret_cast<const float4*>(Kbase + (size_t)d * MP_ + m4);
        *reinterpret_cast<float4*>(&Vs[d * KV_LD + m4]) =
            *reinterpret_cast<const float4*>(Vbase + (size_t)d * MP_ + m4);
    }
    if (tid < 80)
        msk[tid] = (tid < M_ && mask[b * M_ + tid] != 0) ? 0.0f : -1e30f;
    __syncthreads();

    // -------- Phase 1: S = Q @ K^T (warp w -> 16-row band, 5 col frags) ------
    {
        wmma::fragment<wmma::accumulator, 16, 16, 8, float> sacc[5];
#pragma unroll
        for (int j = 0; j < 5; j++) wmma::fill_fragment(sacc[j], 0.0f);
#pragma unroll
        for (int kf = 0; kf < 8; kf++) {      // d = kf*8
            wmma::fragment<wmma::matrix_a, 16, 16, 8, wmma::precision::tf32,
                           wmma::col_major> a;
            wmma::load_matrix_sync(a, Qbase + (size_t)(kf * 8) * N_ + wid * 16, N_);
#pragma unroll
            for (int j = 0; j < 5; j++) {
                wmma::fragment<wmma::matrix_b, 16, 16, 8, wmma::precision::tf32,
                               wmma::row_major> kb;
                wmma::load_matrix_sync(kb, Ks + (kf * 8) * KV_LD + j * 16, KV_LD);
                wmma::mma_sync(sacc[j], a, kb, sacc[j]);
            }
        }
        // store S column-major: tile (q0=wid*16, m0=j*16) at Ssm + q0 + m0*SQ_LD
#pragma unroll
        for (int j = 0; j < 5; j++)
            wmma::store_matrix_sync(Ssm + wid * 16 + (j * 16) * SQ_LD, sacc[j],
                                    SQ_LD, wmma::mem_col_major);
    }
    __syncthreads();

    // -------- Softmax: one thread per query row (CONFLICT-FREE: bank=q) -----
    if (tid < 128) {
        const int q = tid;
        float mx = -1e30f;
#pragma unroll 7
        for (int m = 0; m < M_; m++) {
            const float s = Ssm[q + m * SQ_LD] * SCALE_ + msk[m];
            Ssm[q + m * SQ_LD] = s;
            mx = fmaxf(mx, s);
        }
        float sum = 0.0f;
#pragma unroll 7
        for (int m = 0; m < M_; m++) {
            const float p = __expf(Ssm[q + m * SQ_LD] - mx);
            Ssm[q + m * SQ_LD] = p;
            sum += p;
        }
        const float inv = 1.0f / sum;
#pragma unroll 7
        for (int m = 0; m < M_; m++)
            Ssm[q + m * SQ_LD] = tf32r(Ssm[q + m * SQ_LD] * inv);
        Ssm[q + 77 * SQ_LD] = 0.0f;           // kill padded keys
        Ssm[q + 78 * SQ_LD] = 0.0f;
        Ssm[q + 79 * SQ_LD] = 0.0f;
    }
    __syncthreads();

    // -------- Phase 2: O = P @ V (P = matrix_a col_major, ld SQ_LD) ----------
    {
        wmma::fragment<wmma::accumulator, 16, 16, 8, float> oacc[4];
#pragma unroll
        for (int j = 0; j < 4; j++) wmma::fill_fragment(oacc[j], 0.0f);
#pragma unroll
        for (int kf = 0; kf < 10; kf++) {     // m = kf*8
            wmma::fragment<wmma::matrix_a, 16, 16, 8, wmma::precision::tf32,
                           wmma::col_major> a;
            wmma::load_matrix_sync(a, Ssm + wid * 16 + (kf * 8) * SQ_LD, SQ_LD);
#pragma unroll
            for (int j = 0; j < 4; j++) {
                wmma::fragment<wmma::matrix_b, 16, 16, 8, wmma::precision::tf32,
                               wmma::col_major> vb;
                wmma::load_matrix_sync(vb, Vs + (j * 16) * KV_LD + kf * 8, KV_LD);
                wmma::mma_sync(oacc[j], a, vb, oacc[j]);
            }
        }
        float* obase = out + ((size_t)(b * C_ + h * HD_)) * N_ + n0 + wid * 16;
#pragma unroll
        for (int j = 0; j < 4; j++)
            wmma::store_matrix_sync(obase + (size_t)(j * 16) * N_, oacc[j],
                                    N_, wmma::mem_col_major);
    }
}

// ---------------------------------------------------------------------------
// kernel_launch — inputs: 0:x 1:text_emb 2:attention_mask 3:Wq 4:bq 5:Wk 6:bk 7:Wv 8:bv
// ---------------------------------------------------------------------------
extern "C" void kernel_launch(void* const* d_in, const int* in_sizes, int n_in,
                              void* d_out, int out_size) {
    (void)in_sizes; (void)n_in; (void)out_size;
    const float* x    = (const float*)d_in[0];
    const float* text = (const float*)d_in[1];
    const int*   mask = (const int*)d_in[2];
    const float* Wq   = (const float*)d_in[3];
    const float* bq   = (const float*)d_in[4];
    const float* Wk   = (const float*)d_in[5];
    const float* bk   = (const float*)d_in[6];
    const float* Wv   = (const float*)d_in[7];
    const float* bv   = (const float*)d_in[8];
    float* out = (float*)d_out;

    cudaFuncSetAttribute(gemm_q_kernel,  cudaFuncAttributeMaxDynamicSharedMemorySize,
                         GEMM_SMEM);
    cudaFuncSetAttribute(gemm_kv_kernel, cudaFuncAttributeMaxDynamicSharedMemorySize,
                         GEMM_SMEM);
    cudaFuncSetAttribute(attn_kernel, cudaFuncAttributeMaxDynamicSharedMemorySize,
                         ATTN_SMEM_BYTES);

    round_all_kernel<<<1184, 256>>>(Wq, Wk, Wv, text);
    gemm_kv_kernel<<<dim3(1, 4, 64), 128, GEMM_SMEM>>>(bk, bv);
    gemm_q_kernel<<<dim3(8, 4, 32), 128, GEMM_SMEM>>>(x, bq);
    attn_kernel<<<dim3(8, 8, 32), 256, ATTN_SMEM_BYTES>>>(mask, out);
}

// round 15
// speedup vs baseline: 1.1339x; 1.0357x over previous
#include <cuda_runtime.h>
#include <cuda_bf16.h>
#include <mma.h>
#include <cstdint>

using namespace nvcuda;

// Shapes (fixed by the reference)
#define B_   32
#define C_   512
#define N_   1024       // H*W
#define M_   77
#define MP_  128        // padded M
#define TD_  768
#define NH_  8
#define HD_  64
#define SCALE_ 0.125f   // 1/sqrt(64)

// Scratch (static __device__ — allocation-free per harness rules)
__device__ float g_Qt[B_ * C_ * N_];     // 64 MB  Qt[b][c][n]  (tf32-rounded)
__device__ float g_Kt[B_ * C_ * MP_];    //  8 MB  (tf32-rounded)
__device__ float g_Vt[B_ * C_ * MP_];    //  8 MB  (tf32-rounded)
__device__ float g_Wqr[C_ * C_];         //  1 MB  tf32-rounded operands
__device__ float g_Wkr[C_ * TD_];
__device__ float g_Wvr[C_ * TD_];
__device__ float g_tr[B_ * M_ * TD_];    //  7.6 MB

// tf32 round-to-nearest
__device__ __forceinline__ float tf32r(float f) {
    uint32_t u;
    asm("cvt.rna.tf32.f32 %0, %1;" : "=r"(u) : "f"(f));
    return __uint_as_float(u);
}
__device__ __forceinline__ uint32_t smem_u32(const void* p) {
    uint32_t a;
    asm("{ .reg .u64 t; cvta.to.shared.u64 t, %1; cvt.u32.u64 %0, t; }"
        : "=r"(a) : "l"(p));
    return a;
}
__device__ __forceinline__ void cp16(uint32_t dst, const float* src) {
    asm volatile("cp.async.cg.shared.global [%0], [%1], 16;"
                 :: "r"(dst), "l"(src));
}
// zero-fill variant: src-size 0 -> 16 bytes of zeros, src not dereferenced
__device__ __forceinline__ void cp16z(uint32_t dst, const float* src, bool valid) {
    const int sz = valid ? 16 : 0;
    asm volatile("cp.async.cg.shared.global [%0], [%1], 16, %2;"
                 :: "r"(dst), "l"(src), "r"(sz));
}

// ---------------------------------------------------------------------------
// 0) Pre-round fp32 -> tf32 (weights + text), single merged launch
// ---------------------------------------------------------------------------
__global__ void round_all_kernel(const float* __restrict__ Wq,
                                 const float* __restrict__ Wk,
                                 const float* __restrict__ Wv,
                                 const float* __restrict__ text) {
    const int stride = gridDim.x * blockDim.x;
    const int gid = blockIdx.x * blockDim.x + threadIdx.x;
    const float* srcs[4] = { Wq, Wk, Wv, text };
    float* dsts[4] = { g_Wqr, g_Wkr, g_Wvr, g_tr };
    const int n4s[4] = { (C_ * C_) / 4, (C_ * TD_) / 4, (C_ * TD_) / 4,
                         (B_ * M_ * TD_) / 4 };
#pragma unroll
    for (int a = 0; a < 4; a++) {
        const float4* s = reinterpret_cast<const float4*>(srcs[a]);
        float4* d = reinterpret_cast<float4*>(dsts[a]);
        for (int i = gid; i < n4s[a]; i += stride) {
            float4 v = s[i];
            v.x = tf32r(v.x); v.y = tf32r(v.y); v.z = tf32r(v.z); v.w = tf32r(v.w);
            d[i] = v;
        }
    }
}

// ===========================================================================
// tf32 WMMA GEMM (R11 config — measured best): C[m][n] = A[m][k] @ B + bias[m]
//   block 128x128, 4 warps (2m x 2n), warp tile 64x64 = 4x4 wmma frags,
//   k-tile 32, double-buffered cp.async staging, 2 blocks/SM.
//   A pre-rounded tf32. BCVT: convert B fragments in-register (Q path, raw x).
//   Epilogue writes tf32-rounded C (consumed by tensor-core attention).
// ===========================================================================
#define A_LD   36
#define BQ_LD  132
#define BC_LD  36
#define A_FLOATS   (128 * A_LD)          // 4608
#define B_FLOATS   (128 * BC_LD)         // 4608 (>= 32*BQ_LD = 4224)
#define BUF_FLOATS (A_FLOATS + B_FLOATS) // 9216
#define GEMM_SMEM  (2 * BUF_FLOATS * 4)  // 73728 bytes

template<bool BCOL, bool BCVT>
__device__ __forceinline__ void gemm_body(
    const float* __restrict__ A, const float* __restrict__ Bsrc,
    float* __restrict__ Cout, const float* __restrict__ bias,
    int K, int lda, int ldb, int ldc)
{
    extern __shared__ float smem[];
    const uint32_t smem_addr = smem_u32(smem);
    const int tid = threadIdx.x;          // 128 threads
    const int wid = tid >> 5, lane = tid & 31;
    const int wm = wid >> 1, wn = wid & 1;        // 2 x 2 warp grid
    const int rowBase = blockIdx.y << 7;
    const int colBase = blockIdx.x << 7;

    wmma::fragment<wmma::accumulator, 16, 16, 8, float> c[4][4];
#pragma unroll
    for (int i = 0; i < 4; i++)
#pragma unroll
        for (int j = 0; j < 4; j++) wmma::fill_fragment(c[i][j], 0.0f);

    auto stage = [&](int kt, int buf) {
        const uint32_t sA = smem_addr + buf * (BUF_FLOATS * 4);
        const uint32_t sB = sA + A_FLOATS * 4;
        const float* baseA = A + (size_t)rowBase * lda + kt * 32;
#pragma unroll
        for (int r4 = 0; r4 < 8; r4++) {            // A tile: [128][32]
            const int i4 = tid + (r4 << 7);
            const int row = i4 >> 3, c4 = (i4 & 7) << 2;
            cp16(sA + (uint32_t)(row * A_LD + c4) * 4, baseA + (size_t)row * lda + c4);
        }
        if (!BCOL) {                                 // B tile: [k=32][n=128]
            const float* baseB = Bsrc + (size_t)(kt * 32) * ldb + colBase;
#pragma unroll
            for (int r4 = 0; r4 < 8; r4++) {
                const int i4 = tid + (r4 << 7);
                const int k = i4 >> 5, n4 = (i4 & 31) << 2;
                cp16(sB + (uint32_t)(k * BQ_LD + n4) * 4, baseB + (size_t)k * ldb + n4);
            }
        } else {                                     // B tile: [n=128][k=32], pad n>=M_
            const float* baseB = Bsrc + kt * 32;
#pragma unroll
            for (int r4 = 0; r4 < 8; r4++) {
                const int i4 = tid + (r4 << 7);
                const int n = i4 >> 3, k4 = (i4 & 7) << 2;
                cp16z(sB + (uint32_t)(n * BC_LD + k4) * 4, baseB + (size_t)n * ldb + k4,
                      n < M_);
            }
        }
    };

    const int nkt = K >> 5;
    stage(0, 0);
    asm volatile("cp.async.commit_group;" ::: "memory");

    for (int kt = 0; kt < nkt; kt++) {
        const int buf = kt & 1;
        if (kt + 1 < nkt) {
            stage(kt + 1, buf ^ 1);
            asm volatile("cp.async.commit_group;" ::: "memory");
            asm volatile("cp.async.wait_group 1;" ::: "memory");
        } else {
            asm volatile("cp.async.wait_group 0;" ::: "memory");
        }
        __syncthreads();

        const float* As = smem + buf * BUF_FLOATS;
        const float* Bs = As + A_FLOATS;
#pragma unroll
        for (int ks = 0; ks < 4; ks++) {
            wmma::fragment<wmma::matrix_a, 16, 16, 8, wmma::precision::tf32,
                           wmma::row_major> a[4];
#pragma unroll
            for (int i = 0; i < 4; i++)
                wmma::load_matrix_sync(a[i], As + (wm * 64 + i * 16) * A_LD + ks * 8, A_LD);
#pragma unroll
            for (int j = 0; j < 4; j++) {
                if (!BCOL) {
                    wmma::fragment<wmma::matrix_b, 16, 16, 8, wmma::precision::tf32,
                                   wmma::row_major> b;
                    wmma::load_matrix_sync(b, Bs + ks * 8 * BQ_LD + (wn * 64 + j * 16),
                                           BQ_LD);
                    if (BCVT) {
#pragma unroll
                        for (int t = 0; t < b.num_elements; t++)
                            b.x[t] = wmma::__float_to_tf32(b.x[t]);
                    }
#pragma unroll
                    for (int i = 0; i < 4; i++) wmma::mma_sync(c[i][j], a[i], b, c[i][j]);
                } else {
                    wmma::fragment<wmma::matrix_b, 16, 16, 8, wmma::precision::tf32,
                                   wmma::col_major> b;
                    wmma::load_matrix_sync(b, Bs + (wn * 64 + j * 16) * BC_LD + ks * 8,
                                           BC_LD);
                    if (BCVT) {
#pragma unroll
                        for (int t = 0; t < b.num_elements; t++)
                            b.x[t] = wmma::__float_to_tf32(b.x[t]);
                    }
#pragma unroll
                    for (int i = 0; i < 4; i++) wmma::mma_sync(c[i][j], a[i], b, c[i][j]);
                }
            }
        }
        __syncthreads();   // staging buffers free for next prefetch / epilogue
    }

    // Epilogue: per-warp 16x16 smem patch, add bias, tf32-round, write C
    float* patch = smem + wid * 256;
#pragma unroll
    for (int i = 0; i < 4; i++) {
        const int row0 = rowBase + wm * 64 + i * 16;
#pragma unroll
        for (int j = 0; j < 4; j++) {
            const int col0 = colBase + wn * 64 + j * 16;
            wmma::store_matrix_sync(patch, c[i][j], 16, wmma::mem_row_major);
            __syncwarp();
#pragma unroll
            for (int e = lane; e < 256; e += 32) {
                const int r = e >> 4, cc = e & 15;
                Cout[(size_t)(row0 + r) * ldc + col0 + cc] =
                    tf32r(patch[e] + bias[row0 + r]);
            }
            __syncwarp();
        }
    }
}

// Qt[b] = Wq(512x512) @ x[b](512x1024) + bq   grid (8, 4, 32); B = raw x (cvt in reg)
__global__ __launch_bounds__(128, 2)
void gemm_q_kernel(const float* __restrict__ x, const float* __restrict__ bq) {
    const int b = blockIdx.z;
    gemm_body<false, true>(g_Wqr, x + (size_t)b * C_ * N_, g_Qt + (size_t)b * C_ * N_,
                           bq, C_, C_, N_, N_);
}

// Kt/Vt[b] = W(512x768) @ text[b]^T + bias   grid (1, 4, 64), z = 2b+isV
__global__ __launch_bounds__(128, 2)
void gemm_kv_kernel(const float* __restrict__ bk, const float* __restrict__ bv) {
    const int z = blockIdx.z;
    const int b = z >> 1;
    const bool isV = (z & 1) != 0;
    gemm_body<true, false>(isV ? g_Wvr : g_Wkr, g_tr + (size_t)b * M_ * TD_,
                           (isV ? g_Vt : g_Kt) + (size_t)b * C_ * MP_,
                           isV ? bv : bk, TD_, TD_, TD_, MP_);
}

// ===========================================================================
// WMMA attention v6: 128-query blocks, 256 thr (8 warps), 16-row bands.
//   NEW vs v5:
//   (a) Q tile staged via cp.async into the (dead-during-phase-1) Ssm region
//       — coalesced global reads, phase 1 runs entirely from smem; after a
//       barrier the region is overwritten with S.
//   (b) softmax uses ALL 256 threads: each row split between a thread pair at
//       m=36 (bank offset 4*36 = 16 mod 32 -> still conflict-free), one
//       shfl_xor each for max and sum.
//   S stored column-major: S(q,m) at Ssm[q + m*SQ_LD].
// ===========================================================================
#define SQ_LD 132   // column stride for S and staged Q (mult of 4, coprime banks)
#define KV_LD 84
#define S_FLOATS (SQ_LD * 80)                       // 10560 (Q needs <= 8444)
#define ATTN_SMEM_FLOATS (S_FLOATS + 2 * 64 * KV_LD + 80)
#define ATTN_SMEM_BYTES  (ATTN_SMEM_FLOATS * 4)     // 85568 B -> 2 blocks/SM

__global__ __launch_bounds__(256, 2)
void attn_kernel(const int* __restrict__ mask, float* __restrict__ out) {
    extern __shared__ float sm[];
    float* Ssm = sm;                         // phase1: Q(n,d)=Ssm[n + d*SQ_LD]
                                             // phase2: S(q,m)=Ssm[q + m*SQ_LD]
    float* Ks  = sm + S_FLOATS;              // [64][KV_LD]  (d, m)
    float* Vs  = Ks + 64 * KV_LD;            // [64][KV_LD]  (d, m)
    float* msk = Vs + 64 * KV_LD;            // [80]
    const uint32_t sm_addr = smem_u32(sm);

    const int tid = threadIdx.x;
    const int wid = tid >> 5;
    const int b = blockIdx.z, h = blockIdx.y;
    const int n0 = blockIdx.x << 7;          // 128-query tile

    const float* Qbase = g_Qt + ((size_t)(b * C_ + h * HD_)) * N_ + n0; // (n,d)=ptr[d*N_+n]
    const float* Kbase = g_Kt + ((size_t)(b * C_ + h * HD_)) * MP_;     // (d,m)=ptr[d*MP_+m]
    const float* Vbase = g_Vt + ((size_t)(b * C_ + h * HD_)) * MP_;

    // -------- Stage K, V and Q via cp.async (all coalesced) ------------------
    const uint32_t KsA = sm_addr + (uint32_t)(S_FLOATS * 4);
    const uint32_t VsA = KsA + 64 * KV_LD * 4;
    for (int i = tid; i < 64 * 20; i += 256) {       // K,V: [64 d][80 m]
        const int d = i / 20, m4 = (i % 20) << 2;
        cp16(KsA + (uint32_t)(d * KV_LD + m4) * 4, Kbase + (size_t)d * MP_ + m4);
        cp16(VsA + (uint32_t)(d * KV_LD + m4) * 4, Vbase + (size_t)d * MP_ + m4);
    }
    for (int i = tid; i < 64 * 32; i += 256) {       // Q: [64 d][128 n] rows
        const int d = i >> 5, n4 = (i & 31) << 2;
        cp16(sm_addr + (uint32_t)(n4 + d * SQ_LD) * 4, Qbase + (size_t)d * N_ + n4);
    }
    asm volatile("cp.async.commit_group;" ::: "memory");
    if (tid < 80)
        msk[tid] = (tid < M_ && mask[b * M_ + tid] != 0) ? 0.0f : -1e30f;
    asm volatile("cp.async.wait_group 0;" ::: "memory");
    __syncthreads();

    // -------- Phase 1: S = Q @ K^T (warp w -> 16-row band, 5 col frags) ------
    wmma::fragment<wmma::accumulator, 16, 16, 8, float> sacc[5];
#pragma unroll
    for (int j = 0; j < 5; j++) wmma::fill_fragment(sacc[j], 0.0f);
#pragma unroll
    for (int kf = 0; kf < 8; kf++) {      // d = kf*8
        wmma::fragment<wmma::matrix_a, 16, 16, 8, wmma::precision::tf32,
                       wmma::col_major> a;
        wmma::load_matrix_sync(a, Ssm + wid * 16 + (kf * 8) * SQ_LD, SQ_LD);
#pragma unroll
        for (int j = 0; j < 5; j++) {
            wmma::fragment<wmma::matrix_b, 16, 16, 8, wmma::precision::tf32,
                           wmma::row_major> kb;
            wmma::load_matrix_sync(kb, Ks + (kf * 8) * KV_LD + j * 16, KV_LD);
            wmma::mma_sync(sacc[j], a, kb, sacc[j]);
        }
    }
    __syncthreads();   // all warps done READING Q from Ssm before overwrite
    // store S column-major: tile (q0=wid*16, m0=j*16) at Ssm + q0 + m0*SQ_LD
#pragma unroll
    for (int j = 0; j < 5; j++)
        wmma::store_matrix_sync(Ssm + wid * 16 + (j * 16) * SQ_LD, sacc[j],
                                SQ_LD, wmma::mem_col_major);
    __syncthreads();

    // -------- Softmax: one thread PAIR per row (conflict-free, all warps) ----
    {
        const int q = tid >> 1, half = tid & 1;
        const int mlo = half ? 36 : 0;
        const int mhi = half ? M_ : 36;
        float mx = -1e30f;
        for (int m = mlo; m < mhi; m++) {
            const float s = Ssm[q + m * SQ_LD] * SCALE_ + msk[m];
            Ssm[q + m * SQ_LD] = s;
            mx = fmaxf(mx, s);
        }
        mx = fmaxf(mx, __shfl_xor_sync(0xFFFFFFFFu, mx, 1));
        float sum = 0.0f;
        for (int m = mlo; m < mhi; m++) {
            const float p = __expf(Ssm[q + m * SQ_LD] - mx);
            Ssm[q + m * SQ_LD] = p;
            sum += p;
        }
        sum += __shfl_xor_sync(0xFFFFFFFFu, sum, 1);
        const float inv = 1.0f / sum;
        for (int m = mlo; m < mhi; m++)
            Ssm[q + m * SQ_LD] = tf32r(Ssm[q + m * SQ_LD] * inv);
        if (half) {                                   // kill padded keys
            Ssm[q + 77 * SQ_LD] = 0.0f;
            Ssm[q + 78 * SQ_LD] = 0.0f;
            Ssm[q + 79 * SQ_LD] = 0.0f;
        }
    }
    __syncthreads();

    // -------- Phase 2: O = P @ V (P = matrix_a col_major, ld SQ_LD) ----------
    {
        wmma::fragment<wmma::accumulator, 16, 16, 8, float> oacc[4];
#pragma unroll
        for (int j = 0; j < 4; j++) wmma::fill_fragment(oacc[j], 0.0f);
#pragma unroll
        for (int kf = 0; kf < 10; kf++) {     // m = kf*8
            wmma::fragment<wmma::matrix_a, 16, 16, 8, wmma::precision::tf32,
                           wmma::col_major> a;
            wmma::load_matrix_sync(a, Ssm + wid * 16 + (kf * 8) * SQ_LD, SQ_LD);
#pragma unroll
            for (int j = 0; j < 4; j++) {
                wmma::fragment<wmma::matrix_b, 16, 16, 8, wmma::precision::tf32,
                               wmma::col_major> vb;
                wmma::load_matrix_sync(vb, Vs + (j * 16) * KV_LD + kf * 8, KV_LD);
                wmma::mma_sync(oacc[j], a, vb, oacc[j]);
            }
        }
        float* obase = out + ((size_t)(b * C_ + h * HD_)) * N_ + n0 + wid * 16;
#pragma unroll
        for (int j = 0; j < 4; j++)
            wmma::store_matrix_sync(obase + (size_t)(j * 16) * N_, oacc[j],
                                    N_, wmma::mem_col_major);
    }
}

// ---------------------------------------------------------------------------
// kernel_launch — inputs: 0:x 1:text_emb 2:attention_mask 3:Wq 4:bq 5:Wk 6:bk 7:Wv 8:bv
// ---------------------------------------------------------------------------
extern "C" void kernel_launch(void* const* d_in, const int* in_sizes, int n_in,
                              void* d_out, int out_size) {
    (void)in_sizes; (void)n_in; (void)out_size;
    const float* x    = (const float*)d_in[0];
    const float* text = (const float*)d_in[1];
    const int*   mask = (const int*)d_in[2];
    const float* Wq   = (const float*)d_in[3];
    const float* bq   = (const float*)d_in[4];
    const float* Wk   = (const float*)d_in[5];
    const float* bk   = (const float*)d_in[6];
    const float* Wv   = (const float*)d_in[7];
    const float* bv   = (const float*)d_in[8];
    float* out = (float*)d_out;

    cudaFuncSetAttribute(gemm_q_kernel,  cudaFuncAttributeMaxDynamicSharedMemorySize,
                         GEMM_SMEM);
    cudaFuncSetAttribute(gemm_kv_kernel, cudaFuncAttributeMaxDynamicSharedMemorySize,
                         GEMM_SMEM);
    cudaFuncSetAttribute(attn_kernel, cudaFuncAttributeMaxDynamicSharedMemorySize,
                         ATTN_SMEM_BYTES);

    round_all_kernel<<<1184, 256>>>(Wq, Wk, Wv, text);
    gemm_kv_kernel<<<dim3(1, 4, 64), 128, GEMM_SMEM>>>(bk, bv);
    gemm_q_kernel<<<dim3(8, 4, 32), 128, GEMM_SMEM>>>(x, bq);
    attn_kernel<<<dim3(8, 8, 32), 256, ATTN_SMEM_BYTES>>>(mask, out);
}